// round 15
// baseline (speedup 1.0000x reference)
#include <cuda_runtime.h>
#include <cuda_bf16.h>

// ProbabilityAdjustedLoss: B=8388608 rows, logits [B,2] fp32, labels [B] int32.
// Streaming reduction: 100.7 MB in, 4 B out. Working set fits in 126 MB L2;
// graph replays run warm (best wall 14.85us < cold-cache ncu ~19.9us).
// Wall BW ~6.8 TB/s ~= the LTS chip cap (path-independent) — at the binding
// hardware ceiling. CONVERGED — hold steady; residual spread is environment.
//
// Evidence ledger (structural probes, all resolved):
//  - single resident wave: 1184 x 256 = 64 warps/SM (HW max occupancy)  [R6 WIN]
//  - 4 rows/iter, 3 front-batched LDG.128; 6 loads regressed (L1tex q)  [R4 FAIL]
//  - stride-2 float4 pair: 2nd load is an L1 sector hit on the 1st's
//    sectors -> traffic already dense; dense remap adds a 4th load       [R14 analysis]
//  - division-free math: -log(p_sel)=log(1+exp(±(l1-l0))), MUFU rcp
//    only feeds the stop-gradient weight; bit-exact (rel_err 0.0)       [R4/R5 WIN]
//  - DEFAULT-policy loads; __ldcs evict-first killed warm-L2 (+6us)     [R9 FAIL]
//  - L2 protect/stream partitioning: neutral                            [R8 NEUTRAL]
//  - deterministic Q32.32 integer-atomic fused epilogue                 [R3/R5 WIN]
//  - identical binaries: wall {14.85,14.88,15.23,16.38,16.45,16.86,23.8}us,
//    cold-ncu 19.7-21.3us tracking wall -> DVFS clock-window variance   [R10-R14]

#define NBLOCKS 1184   // 148 SMs * 8 CTAs/SM = exactly one full wave
#define NTHREADS 256
#define FIXED_SCALE 4294967296.0  // 2^32

__device__ unsigned long long g_acc = 0ULL;
__device__ unsigned int g_ticket = 0u;

__device__ __forceinline__ float row_loss(float l0, float l1, int lab) {
    const bool stable = (lab == 0);
    const float d = l1 - l0;
    const float x = stable ? d : -d;         // x s.t. p_sel = 1/(1+exp(x))
    const float u = 1.0f + __expf(x);        // 1/p_sel
    const float p = __fdividef(1.0f, u);     // MUFU rcp, weight path only

    // label-selected weight constants; branchless clamp-fma-clamp
    const float thresh = stable ? 0.95f : 0.05f;
    const float slope  = stable ? 10.0f : (1.0f / 0.95f);
    const float basev  = stable ? 1.0f  : 2.0f;
    const float floorv = stable ? 0.1f  : 0.5f;
    const float w = fmaxf(floorv, fmaf(-slope, fmaxf(0.0f, p - thresh), basev));

    return w * __logf(u);                    // = -w * log(p_sel)
}

__global__ void __launch_bounds__(NTHREADS, 8)
loss_fused_kernel(const float4* __restrict__ logits2,  // 2 rows per float4
                  const int4* __restrict__ labels4,    // 4 labels per int4
                  float* __restrict__ out,
                  int nquads, float inv_B) {           // groups of 4 rows
    float acc = 0.0f;
    const int stride = gridDim.x * blockDim.x;
    for (int i = blockIdx.x * blockDim.x + threadIdx.x; i < nquads; i += stride) {
        // 3 front-batched wide loads (MLP_p1 = 3), default cache policy
        const float4 lgA = logits2[2 * i + 0];
        const float4 lgB = logits2[2 * i + 1];
        const int4   lb  = labels4[i];
        acc += row_loss(lgA.x, lgA.y, lb.x);
        acc += row_loss(lgA.z, lgA.w, lb.y);
        acc += row_loss(lgB.x, lgB.y, lb.z);
        acc += row_loss(lgB.z, lgB.w, lb.w);
    }

    // Block reduction
    __shared__ float sdata[NTHREADS];
    sdata[threadIdx.x] = acc;
    __syncthreads();
    #pragma unroll
    for (int s = NTHREADS / 2; s > 32; s >>= 1) {
        if (threadIdx.x < s) sdata[threadIdx.x] += sdata[threadIdx.x + s];
        __syncthreads();
    }

    __shared__ bool s_is_last;
    if (threadIdx.x < 32) {
        float v = sdata[threadIdx.x] + sdata[threadIdx.x + 32];
        #pragma unroll
        for (int off = 16; off > 0; off >>= 1)
            v += __shfl_down_sync(0xFFFFFFFFu, v, off);

        if (threadIdx.x == 0) {
            // Deterministic cross-block combine (integer add is associative ->
            // identical result on every replay regardless of arrival order).
            long long q = llrint((double)v * FIXED_SCALE);
            atomicAdd(&g_acc, (unsigned long long)q);
            __threadfence();
            unsigned int t = atomicAdd(&g_ticket, 1u);
            s_is_last = (t == (unsigned int)(gridDim.x - 1));
        }
    }
    __syncthreads();

    // Last block writes the mean and resets state for the next graph replay.
    if (s_is_last && threadIdx.x == 0) {
        unsigned long long total = atomicAdd(&g_acc, 0ULL);  // coherent read
        out[0] = (float)(((double)(long long)total / FIXED_SCALE) * (double)inv_B);
        g_acc = 0ULL;
        g_ticket = 0u;
    }
}

extern "C" void kernel_launch(void* const* d_in, const int* in_sizes, int n_in,
                              void* d_out, int out_size) {
    const float4* logits2 = (const float4*)d_in[0];  // [B,2] fp32 -> B/2 float4
    const int4*   labels4 = (const int4*)d_in[1];    // [B] int32 -> B/4 int4
    const int B = in_sizes[1];                       // label element count
    const int nquads = B / 4;

    loss_fused_kernel<<<NBLOCKS, NTHREADS>>>(logits2, labels4, (float*)d_out,
                                             nquads, 1.0f / (float)B);
}

// round 16
// speedup vs baseline: 1.0524x; 1.0524x over previous
#include <cuda_runtime.h>
#include <cuda_bf16.h>

// ProbabilityAdjustedLoss: B=8388608 rows, logits [B,2] fp32, labels [B] int32.
// Streaming reduction: 100.7 MB in, 4 B out. Working set fits in 126 MB L2;
// graph replays run warm (best wall 14.85us < cold-cache ncu ~19.9us).
// Wall BW ~6.8 TB/s ~= the LTS chip cap (path-independent) — at the binding
// hardware ceiling. CONVERGED — hold steady; residual spread is environment.
//
// Evidence ledger (structural probes, all resolved):
//  - single resident wave: 1184 x 256 = 64 warps/SM (HW max occupancy)  [R6 WIN]
//  - 4 rows/iter, 3 front-batched LDG.128; 6 loads regressed (L1tex q)  [R4 FAIL]
//  - stride-2 float4 pair: 2nd load is an L1 sector hit on the 1st's
//    sectors -> traffic already dense; dense remap adds a 4th load      [R14 analysis]
//  - 256-bit loads / 512-thread blocks: cannot raise the LTS byte cap;
//    not LSU/issue-bound (37%) -> no gain, rejected                     [R15 analysis]
//  - division-free math: -log(p_sel)=log(1+exp(±(l1-l0))), MUFU rcp
//    only feeds the stop-gradient weight; bit-exact (rel_err 0.0)       [R4/R5 WIN]
//  - DEFAULT-policy loads; __ldcs evict-first killed warm-L2 (+6us)     [R9 FAIL]
//  - L2 protect/stream partitioning: neutral                            [R8 NEUTRAL]
//  - deterministic Q32.32 integer-atomic fused epilogue                 [R3/R5 WIN]
//  - identical binaries: wall {14.85,14.88,15.23,16.38,16.45,16.70,
//    16.86,23.8}us, cold-ncu flat 19.7-21.3us -> DVFS clock-window
//    variance, not kernel behavior                                      [R10-R15]

#define NBLOCKS 1184   // 148 SMs * 8 CTAs/SM = exactly one full wave
#define NTHREADS 256
#define FIXED_SCALE 4294967296.0  // 2^32

__device__ unsigned long long g_acc = 0ULL;
__device__ unsigned int g_ticket = 0u;

__device__ __forceinline__ float row_loss(float l0, float l1, int lab) {
    const bool stable = (lab == 0);
    const float d = l1 - l0;
    const float x = stable ? d : -d;         // x s.t. p_sel = 1/(1+exp(x))
    const float u = 1.0f + __expf(x);        // 1/p_sel
    const float p = __fdividef(1.0f, u);     // MUFU rcp, weight path only

    // label-selected weight constants; branchless clamp-fma-clamp
    const float thresh = stable ? 0.95f : 0.05f;
    const float slope  = stable ? 10.0f : (1.0f / 0.95f);
    const float basev  = stable ? 1.0f  : 2.0f;
    const float floorv = stable ? 0.1f  : 0.5f;
    const float w = fmaxf(floorv, fmaf(-slope, fmaxf(0.0f, p - thresh), basev));

    return w * __logf(u);                    // = -w * log(p_sel)
}

__global__ void __launch_bounds__(NTHREADS, 8)
loss_fused_kernel(const float4* __restrict__ logits2,  // 2 rows per float4
                  const int4* __restrict__ labels4,    // 4 labels per int4
                  float* __restrict__ out,
                  int nquads, float inv_B) {           // groups of 4 rows
    float acc = 0.0f;
    const int stride = gridDim.x * blockDim.x;
    for (int i = blockIdx.x * blockDim.x + threadIdx.x; i < nquads; i += stride) {
        // 3 front-batched wide loads (MLP_p1 = 3), default cache policy
        const float4 lgA = logits2[2 * i + 0];
        const float4 lgB = logits2[2 * i + 1];
        const int4   lb  = labels4[i];
        acc += row_loss(lgA.x, lgA.y, lb.x);
        acc += row_loss(lgA.z, lgA.w, lb.y);
        acc += row_loss(lgB.x, lgB.y, lb.z);
        acc += row_loss(lgB.z, lgB.w, lb.w);
    }

    // Block reduction
    __shared__ float sdata[NTHREADS];
    sdata[threadIdx.x] = acc;
    __syncthreads();
    #pragma unroll
    for (int s = NTHREADS / 2; s > 32; s >>= 1) {
        if (threadIdx.x < s) sdata[threadIdx.x] += sdata[threadIdx.x + s];
        __syncthreads();
    }

    __shared__ bool s_is_last;
    if (threadIdx.x < 32) {
        float v = sdata[threadIdx.x] + sdata[threadIdx.x + 32];
        #pragma unroll
        for (int off = 16; off > 0; off >>= 1)
            v += __shfl_down_sync(0xFFFFFFFFu, v, off);

        if (threadIdx.x == 0) {
            // Deterministic cross-block combine (integer add is associative ->
            // identical result on every replay regardless of arrival order).
            long long q = llrint((double)v * FIXED_SCALE);
            atomicAdd(&g_acc, (unsigned long long)q);
            __threadfence();
            unsigned int t = atomicAdd(&g_ticket, 1u);
            s_is_last = (t == (unsigned int)(gridDim.x - 1));
        }
    }
    __syncthreads();

    // Last block writes the mean and resets state for the next graph replay.
    if (s_is_last && threadIdx.x == 0) {
        unsigned long long total = atomicAdd(&g_acc, 0ULL);  // coherent read
        out[0] = (float)(((double)(long long)total / FIXED_SCALE) * (double)inv_B);
        g_acc = 0ULL;
        g_ticket = 0u;
    }
}

extern "C" void kernel_launch(void* const* d_in, const int* in_sizes, int n_in,
                              void* d_out, int out_size) {
    const float4* logits2 = (const float4*)d_in[0];  // [B,2] fp32 -> B/2 float4
    const int4*   labels4 = (const int4*)d_in[1];    // [B] int32 -> B/4 int4
    const int B = in_sizes[1];                       // label element count
    const int nquads = B / 4;

    loss_fused_kernel<<<NBLOCKS, NTHREADS>>>(logits2, labels4, (float*)d_out,
                                             nquads, 1.0f / (float)B);
}